// round 1
// baseline (speedup 1.0000x reference)
#include <cuda_runtime.h>
#include <cuda_bf16.h>
#include <math.h>

// Problem constants (fixed shapes for this problem)
#define KSTATES 16
#define CDIM 64
#define TDIM 65536
#define ARP 8          // AR order, kernel size = 9
#define KSZ 9
#define TT 128         // time tile per block

// ---------------- device scratch (no allocations allowed) ----------------
__device__ float g_Linv[KSTATES * CDIM * CDIM];     // L^{-1}, row-major [k][i][j]
__device__ float g_logdet[KSTATES];
__device__ float g_beff[KSTATES * CDIM];            // L^{-1} b
// Paired effective weights: [k][row=p*9+j][c][2] where pair = (ci=2p, ci=2p+1)
// value[e] = Weff[c][(2p+e)*9 + j] = sum_m Linv[k][c][m] * W[k][m][2p+e][j]
__device__ float g_Weff2[KSTATES * 288 * CDIM * 2]; // 589824 floats

// ---------------- packed f32x2 helpers ----------------
__device__ __forceinline__ unsigned long long pack2(float lo, float hi) {
    unsigned long long r;
    asm("mov.b64 %0, {%1, %2};" : "=l"(r) : "f"(lo), "f"(hi));
    return r;
}
__device__ __forceinline__ void unpack2(unsigned long long v, float& lo, float& hi) {
    asm("mov.b64 {%0, %1}, %2;" : "=f"(lo), "=f"(hi) : "l"(v));
}
__device__ __forceinline__ unsigned long long fma2(unsigned long long a,
                                                   unsigned long long b,
                                                   unsigned long long c) {
    unsigned long long d;
    asm("fma.rn.f32x2 %0, %1, %2, %3;" : "=l"(d) : "l"(a), "l"(b), "l"(c));
    return d;
}

// ---------------- 1) Cholesky + inverse + logdet (16 blocks x 64 threads) ----------------
__global__ void chol_kernel(const float* __restrict__ Sigma) {
    const int k = blockIdx.x;
    const int tid = threadIdx.x;  // 64 threads
    __shared__ float S[CDIM * 65];
    __shared__ float X[CDIM * 65];

    for (int idx = tid; idx < CDIM * CDIM; idx += 64) {
        S[(idx >> 6) * 65 + (idx & 63)] = Sigma[k * CDIM * CDIM + idx];
    }
    __syncthreads();

    // right-looking Cholesky, lower triangle
    for (int kk = 0; kk < CDIM; kk++) {
        if (tid == kk) S[kk * 65 + kk] = sqrtf(S[kk * 65 + kk]);
        __syncthreads();
        if (tid > kk) S[tid * 65 + kk] /= S[kk * 65 + kk];
        __syncthreads();
        if (tid > kk) {
            float lik = S[tid * 65 + kk];
            for (int j = kk + 1; j <= tid; j++)
                S[tid * 65 + j] -= lik * S[j * 65 + kk];
        }
        __syncthreads();
    }

    if (tid == 0) {
        float ld = 0.f;
        for (int i = 0; i < CDIM; i++) ld += logf(S[i * 65 + i]);
        g_logdet[k] = 2.f * ld;
    }

    // forward substitution: column c of X = L^{-1}
    const int c = tid;
    for (int i = 0; i < CDIM; i++) {
        float t;
        if (i < c) {
            t = 0.f;
        } else {
            t = (i == c) ? 1.f : 0.f;
            for (int j = c; j < i; j++) t -= S[i * 65 + j] * X[j * 65 + c];
            t /= S[i * 65 + i];
        }
        X[i * 65 + c] = t;
    }
    for (int i = 0; i < CDIM; i++)
        g_Linv[k * CDIM * CDIM + i * CDIM + c] = X[i * 65 + c];
}

// ---------------- 2) Weff = Linv @ W_flat (paired layout), beff = Linv b ----------------
__global__ void weff_kernel(const float* __restrict__ W, const float* __restrict__ b) {
    const int k = blockIdx.x;
    const int tid = threadIdx.x;  // 256 threads
    __shared__ float Ls[CDIM * 65];

    for (int idx = tid; idx < CDIM * CDIM; idx += 256)
        Ls[(idx >> 6) * 65 + (idx & 63)] = g_Linv[k * CDIM * CDIM + idx];
    __syncthreads();

    if (tid < CDIM) {
        float a = 0.f;
        for (int m = 0; m < CDIM; m++) a += Ls[tid * 65 + m] * b[k * CDIM + m];
        g_beff[k * CDIM + tid] = a;
    }

    const float* Wk = W + (size_t)k * CDIM * CDIM * KSZ;  // [m][ci][j]
    for (int o = tid; o < 288 * CDIM; o += 256) {
        const int c = o & 63;
        const int row = o >> 6;       // 0..287
        const int p = row / KSZ;
        const int j = row - p * KSZ;
        float a0 = 0.f, a1 = 0.f;
        for (int m = 0; m < CDIM; m++) {
            float l = Ls[c * 65 + m];
            a0 += l * Wk[(m * CDIM + 2 * p) * KSZ + j];
            a1 += l * Wk[(m * CDIM + 2 * p + 1) * KSZ + j];
        }
        float2* dst = (float2*)&g_Weff2[(((size_t)k * 288 + row) * CDIM + c) * 2];
        *dst = make_float2(a0, a1);
    }
}

// ---------------- 3) fused conv + quadratic form + logprob ----------------
// grid (T/TT, K), 256 threads. smem: Wsm (288*64 f32x2) + xs (32*136 f32x2) + red[TT]
__global__ void __launch_bounds__(256, 1)
main_kernel(const float* __restrict__ x, float* __restrict__ out) {
    extern __shared__ __align__(16) float smem_f[];
    unsigned long long* Wsm = (unsigned long long*)smem_f;        // 288*64 = 18432
    unsigned long long* xs  = Wsm + 288 * CDIM;                   // 32*136 = 4352
    float* red = (float*)(xs + 32 * 136);                         // TT floats

    const int k  = blockIdx.y;
    const int t0 = blockIdx.x * TT;
    const int tid = threadIdx.x;

    // load paired Weff tile (144 KB), contiguous float4 copy
    {
        const float4* src = (const float4*)(g_Weff2 + (size_t)k * 288 * CDIM * 2);
        float4* dst = (float4*)Wsm;
        #pragma unroll
        for (int i = tid; i < 288 * CDIM * 2 / 4; i += 256) dst[i] = src[i];
    }
    // load x tile as (even ci, odd ci) pairs, with causal zero pad
    for (int idx = tid; idx < 32 * 136; idx += 256) {
        const int p = idx / 136;
        const int i = idx - p * 136;
        const int gt = t0 - ARP + i;
        float lo = 0.f, hi = 0.f;
        if (gt >= 0) {
            lo = x[(2 * p) * TDIM + gt];
            hi = x[(2 * p + 1) * TDIM + gt];
        }
        ((float2*)xs)[idx] = make_float2(lo, hi);
    }
    if (tid < TT) red[tid] = 0.f;
    __syncthreads();

    const int lane = tid & 31;
    const int wid  = tid >> 5;
    const int cg = wid >> 2;     // 0..1 : channel group
    const int tg = wid & 3;      // 0..3 : time group
    const int c = cg * 32 + lane;

    unsigned long long acc[32];
    {
        const float bc = g_beff[k * CDIM + c];
        const unsigned long long binit = pack2(bc, 0.f);
        #pragma unroll
        for (int t = 0; t < 32; t++) acc[t] = binit;
    }

    const unsigned long long* xrowbase = xs + tg * 32;
    #pragma unroll 1
    for (int p = 0; p < 32; p++) {
        unsigned long long w2[KSZ];
        const unsigned long long* wr = Wsm + (p * KSZ) * CDIM + c;
        #pragma unroll
        for (int j = 0; j < KSZ; j++) w2[j] = wr[j * CDIM];

        const unsigned long long* xr = xrowbase + p * 136;
        #pragma unroll
        for (int th = 0; th < 32; th += 16) {
            unsigned long long xv[24];
            #pragma unroll
            for (int i = 0; i < 24; i += 2) {
                ulonglong2 v = *(const ulonglong2*)(xr + th + i);
                xv[i] = v.x; xv[i + 1] = v.y;
            }
            #pragma unroll
            for (int t = 0; t < 16; t++) {
                #pragma unroll
                for (int j = 0; j < KSZ; j++)
                    acc[th + t] = fma2(w2[j], xv[t + j], acc[th + t]);
            }
        }
    }

    // z = lo + hi; sum_c z^2 across 64 channels (32 lanes x 2 warps)
    #pragma unroll
    for (int t = 0; t < 32; t++) {
        float lo, hi;
        unpack2(acc[t], lo, hi);
        const float z = lo + hi;
        float s = z * z;
        s += __shfl_xor_sync(0xffffffffu, s, 16);
        s += __shfl_xor_sync(0xffffffffu, s, 8);
        s += __shfl_xor_sync(0xffffffffu, s, 4);
        s += __shfl_xor_sync(0xffffffffu, s, 2);
        s += __shfl_xor_sync(0xffffffffu, s, 1);
        if (lane == 0) atomicAdd(&red[tg * 32 + t], s);
    }
    __syncthreads();

    if (tid < TT) {
        // C*log(2*pi) = 64 * 1.8378770664093453
        const float lp = -0.5f * (117.62413224999810f + g_logdet[k] + red[tid]);
        out[(size_t)k * TDIM + t0 + tid] = lp;
    }
}

// ---------------- launch ----------------
extern "C" void kernel_launch(void* const* d_in, const int* in_sizes, int n_in,
                              void* d_out, int out_size) {
    const float* x     = (const float*)d_in[0];  // [1,64,65536]
    const float* W     = (const float*)d_in[1];  // [16,64,64,9]
    const float* b     = (const float*)d_in[2];  // [16,64]
    const float* Sigma = (const float*)d_in[3];  // [16,64,64]
    float* out = (float*)d_out;                  // [1,16,65536]

    (void)in_sizes; (void)n_in; (void)out_size;

    const int smem_bytes = (288 * CDIM + 32 * 136) * 8 + TT * 4;  // 182784
    cudaFuncSetAttribute(main_kernel, cudaFuncAttributeMaxDynamicSharedMemorySize,
                         smem_bytes);

    chol_kernel<<<KSTATES, 64>>>(Sigma);
    weff_kernel<<<KSTATES, 256>>>(W, b);
    dim3 grid(TDIM / TT, KSTATES);
    main_kernel<<<grid, 256, smem_bytes>>>(x, out);
}

// round 3
// speedup vs baseline: 5.0072x; 5.0072x over previous
#include <cuda_runtime.h>
#include <cuda_fp16.h>
#include <math.h>
#include <stdint.h>

// ---------------- problem constants ----------------
#define KST   16
#define CDIM  64
#define TDIM  65536
#define KTOT  576            // 64*9 contraction length
#define TM    128            // time rows per tile (GEMM M)
#define NKS   36             // K16 steps
#define ASTR  1168           // smem row stride bytes (584 halves)

// ---------------- device scratch ----------------
__device__ float  g_Linv[KST * CDIM * CDIM];
__device__ float  g_logdet[KST];
__device__ float  g_beff[KST * CDIM];
__device__ __half g_WeffH[KST * CDIM * KTOT];   // [k][c][e], e = ci*9+j

// ---------------- helpers ----------------
__device__ __forceinline__ uint32_t s2u(const void* p) {
    uint32_t a;
    asm("{ .reg .u64 t; cvta.to.shared.u64 t, %1; cvt.u32.u64 %0, t; }" : "=r"(a) : "l"(p));
    return a;
}
__device__ __forceinline__ void ldsm4(uint32_t* r, uint32_t addr) {
    asm volatile("ldmatrix.sync.aligned.m8n8.x4.shared.b16 {%0,%1,%2,%3}, [%4];"
                 : "=r"(r[0]), "=r"(r[1]), "=r"(r[2]), "=r"(r[3]) : "r"(addr));
}
__device__ __forceinline__ void mma16816(float* d, const uint32_t* a, const uint32_t* b) {
    asm volatile(
        "mma.sync.aligned.m16n8k16.row.col.f32.f16.f16.f32 "
        "{%0,%1,%2,%3}, {%4,%5,%6,%7}, {%8,%9}, {%0,%1,%2,%3};"
        : "+f"(d[0]), "+f"(d[1]), "+f"(d[2]), "+f"(d[3])
        : "r"(a[0]), "r"(a[1]), "r"(a[2]), "r"(a[3]), "r"(b[0]), "r"(b[1]));
}
__device__ __forceinline__ void cpasync16(uint32_t dst, const void* src) {
    asm volatile("cp.async.cg.shared.global [%0], [%1], 16;" :: "r"(dst), "l"(src));
}
#define CP_COMMIT() asm volatile("cp.async.commit_group;" ::: "memory")
#define CP_WAIT1()  asm volatile("cp.async.wait_group 1;" ::: "memory")

// ================= 1) Cholesky + L^{-1} + logdet + beff =================
__global__ void chol_kernel(const float* __restrict__ Sigma, const float* __restrict__ b) {
    const int k = blockIdx.x;
    const int tid = threadIdx.x;   // 256
    __shared__ float S[CDIM * 65];
    __shared__ float X[CDIM * 65];

    for (int idx = tid; idx < CDIM * CDIM; idx += 256)
        S[(idx >> 6) * 65 + (idx & 63)] = Sigma[k * CDIM * CDIM + idx];
    __syncthreads();

    const int r = tid & 63;
    const int q = tid >> 6;
    for (int kk = 0; kk < CDIM; kk++) {
        if (tid == kk) S[kk * 65 + kk] = sqrtf(S[kk * 65 + kk]);
        __syncthreads();
        if (tid < CDIM && tid > kk) S[tid * 65 + kk] /= S[kk * 65 + kk];
        __syncthreads();
        if (r > kk) {
            const float lik = S[r * 65 + kk];
            for (int j = kk + 1 + q; j <= r; j += 4)
                S[r * 65 + j] -= lik * S[j * 65 + kk];
        }
        __syncthreads();
    }

    if (tid == 0) {
        float ld = 0.f;
        for (int i = 0; i < CDIM; i++) ld += logf(S[i * 65 + i]);
        g_logdet[k] = 2.f * ld;
    }

    if (tid < CDIM) {                         // forward substitution, col c
        const int c = tid;
        for (int i = 0; i < CDIM; i++) {
            float t;
            if (i < c) t = 0.f;
            else {
                t = (i == c) ? 1.f : 0.f;
                for (int j = c; j < i; j++) t -= S[i * 65 + j] * X[j * 65 + c];
                t /= S[i * 65 + i];
            }
            X[i * 65 + c] = t;
        }
    }
    __syncthreads();
    if (tid < CDIM) {
        float a = 0.f;
        for (int m = 0; m < CDIM; m++) a += X[tid * 65 + m] * b[k * CDIM + m];
        g_beff[k * CDIM + tid] = a;
        for (int i = 0; i < CDIM; i++)
            g_Linv[k * CDIM * CDIM + i * CDIM + tid] = X[i * 65 + tid];
    }
}

// ========== 2) Weff = Linv @ W -> fp16 packed [k][c][576] ==========
// grid (8 splits, 16 k), 256 threads. Split s covers e in [72s, 72s+72).
__global__ void weff_pack_kernel(const float* __restrict__ W) {
    const int s = blockIdx.x;
    const int k = blockIdx.y;
    const int tid = threadIdx.x;
    __shared__ float Xs[CDIM * 65];
    __shared__ float Ws[CDIM * 73];

    for (int idx = tid; idx < CDIM * CDIM; idx += 256)
        Xs[(idx >> 6) * 65 + (idx & 63)] = g_Linv[k * CDIM * CDIM + idx];
    for (int idx = tid; idx < CDIM * 72; idx += 256) {
        const int m = idx / 72, e = idx - m * 72;
        Ws[m * 73 + e] = W[k * CDIM * KTOT + m * KTOT + s * 72 + e];
    }
    __syncthreads();

    const int c = tid & 63;
    const int grp = tid >> 6;
    float Lr[CDIM];
    #pragma unroll
    for (int m = 0; m < CDIM; m++) Lr[m] = Xs[c * 65 + m];

    for (int eo = grp; eo < 72; eo += 4) {
        float acc = 0.f;
        #pragma unroll
        for (int m = 0; m < CDIM; m++) acc += Lr[m] * Ws[m * 73 + eo];
        g_WeffH[((size_t)k * CDIM + c) * KTOT + s * 72 + eo] = __float2half(acc);
    }
}

// ================= 3) main: smem im2col A + mma.sync fp16 =================
// smem bytes: A [0,149504), B [149504,224256), beff [224256,228352), logd [,228416)
#define SMA   0
#define SMB   149504
#define SMBE  224256
#define SMLD  228352
#define SMTOT 228416

__device__ __forceinline__ void loadB(uint32_t sbB, int k, int h, int tid) {
    // half h: 288 halves per row starting at byte col h*576; 64 rows x 36 chunks
    #pragma unroll
    for (int i = 0; i < 18; i++) {
        const int lin = i * 128 + tid;          // 0..2303
        const int row = lin / 36, ch = lin - row * 36;
        const uint32_t dst = sbB + row * ASTR + h * 576 + ch * 16;
        const char* src = (const char*)g_WeffH +
                          ((size_t)k * CDIM + row) * (KTOT * 2) + h * 576 + ch * 16;
        cpasync16(dst, src);
    }
}

__global__ void __launch_bounds__(128, 1)
main_kernel(const float* __restrict__ x, float* __restrict__ out) {
    extern __shared__ __align__(1024) char smem[];
    const uint32_t sb = s2u(smem);
    const int tid = threadIdx.x;
    const int lane = tid & 31;
    const int w = tid >> 5;
    const int t0 = blockIdx.x * TM;

    float* beff_s = (float*)(smem + SMBE);
    float* logd_s = (float*)(smem + SMLD);

    // prefetch B for half-steps 0 and 1 (state 0)
    loadB(sb + SMB, 0, 0, tid); CP_COMMIT();
    loadB(sb + SMB, 0, 1, tid); CP_COMMIT();

    // ---- build A (im2col fp16) : thread t owns row t ----
    {
        __half* Arow = (__half*)(smem + SMA + tid * ASTR);
        const int tb = t0 + tid - 8;
        #pragma unroll 4
        for (int p = 0; p < 32; p++) {           // channel pairs (2p, 2p+1)
            float v[18];
            const float* x0 = x + (size_t)(2 * p) * TDIM;
            const float* x1 = x0 + TDIM;
            #pragma unroll
            for (int j = 0; j < 9; j++) {
                const int gt = tb + j;
                v[j]     = (gt >= 0) ? __ldg(x0 + gt) : 0.f;
                v[9 + j] = (gt >= 0) ? __ldg(x1 + gt) : 0.f;
            }
            uint32_t* dst = (uint32_t*)(Arow + p * 18);   // 36B-aligned
            #pragma unroll
            for (int q = 0; q < 9; q++) {
                __half2 hh = __floats2half2_rn(v[2 * q], v[2 * q + 1]);
                dst[q] = *(uint32_t*)&hh;
            }
        }
    }
    for (int idx = tid; idx < KST * CDIM; idx += 128) beff_s[idx] = g_beff[idx];
    if (tid < KST) logd_s[tid] = g_logdet[tid];

    // ldmatrix per-thread base addresses
    const int mat = lane >> 3, lr = lane & 7;
    const uint32_t aBase = sb + SMA + (w * 32 + (mat & 1) * 8 + lr) * ASTR + (mat >> 1) * 16;
    const uint32_t bBase = sb + SMB + ((mat >> 1) * 8 + lr) * ASTR + (mat & 1) * 16;
    const int g = lane >> 2, tig = lane & 3;

    float acc[2][8][4];
    #pragma unroll
    for (int mt = 0; mt < 2; mt++)
        #pragma unroll
        for (int nt = 0; nt < 8; nt++)
            #pragma unroll
            for (int i = 0; i < 4; i++) acc[mt][nt][i] = 0.f;

    CP_WAIT1();              // half-step 0 resident
    __syncthreads();         // A + B(0,0) visible everywhere

    for (int s = 0; s < 2 * KST; s++) {
        const int k = s >> 1, h = s & 1;

        // ---- compute half-step s : k-steps [h*18, h*18+18) ----
        #pragma unroll 2
        for (int kk = h * 18; kk < h * 18 + 18; kk++) {
            uint32_t a[2][4], b[4][4];
            ldsm4(a[0], aBase + kk * 32);
            ldsm4(a[1], aBase + 16 * ASTR + kk * 32);
            #pragma unroll
            for (int np = 0; np < 4; np++)
                ldsm4(b[np], bBase + np * 16 * ASTR + kk * 32);
            #pragma unroll
            for (int mt = 0; mt < 2; mt++)
                #pragma unroll
                for (int nt = 0; nt < 8; nt++)
                    mma16816(acc[mt][nt], a[mt], &b[nt >> 1][(nt & 1) * 2]);
        }

        // ---- epilogue at end of each state ----
        if (h == 1) {
            const float ld = logd_s[k];
            float be0[8], be1[8];
            #pragma unroll
            for (int nt = 0; nt < 8; nt++) {
                float2 v = *(const float2*)&beff_s[k * CDIM + nt * 8 + tig * 2];
                be0[nt] = v.x; be1[nt] = v.y;
            }
            #pragma unroll
            for (int mt = 0; mt < 2; mt++)
                #pragma unroll
                for (int rh = 0; rh < 2; rh++) {
                    float sum = 0.f;
                    #pragma unroll
                    for (int nt = 0; nt < 8; nt++) {
                        const float z0 = acc[mt][nt][rh * 2 + 0] + be0[nt];
                        const float z1 = acc[mt][nt][rh * 2 + 1] + be1[nt];
                        sum = fmaf(z0, z0, sum);
                        sum = fmaf(z1, z1, sum);
                        acc[mt][nt][rh * 2 + 0] = 0.f;
                        acc[mt][nt][rh * 2 + 1] = 0.f;
                    }
                    sum += __shfl_xor_sync(0xffffffffu, sum, 1);
                    sum += __shfl_xor_sync(0xffffffffu, sum, 2);
                    if (tig == 0)
                        out[(size_t)k * TDIM + t0 + w * 32 + mt * 16 + rh * 8 + g] =
                            -0.5f * (117.62413225f + ld + sum);
                }
        }

        __syncthreads();                         // everyone done with buffer of s
        if (s + 2 < 2 * KST) {
            const int s2 = s + 2;
            loadB(sb + SMB, s2 >> 1, s2 & 1, tid);   // reuses buffer of s
        }
        CP_COMMIT();
        if (s + 1 < 2 * KST) {
            CP_WAIT1();                          // half-step s+1 resident
            __syncthreads();
        }
    }
}

// ---------------- launch ----------------
extern "C" void kernel_launch(void* const* d_in, const int* in_sizes, int n_in,
                              void* d_out, int out_size) {
    const float* x     = (const float*)d_in[0];  // [1,64,65536]
    const float* W     = (const float*)d_in[1];  // [16,64,64,9]
    const float* b     = (const float*)d_in[2];  // [16,64]
    const float* Sigma = (const float*)d_in[3];  // [16,64,64]
    float* out = (float*)d_out;                  // [1,16,65536]
    (void)in_sizes; (void)n_in; (void)out_size;

    cudaFuncSetAttribute(main_kernel, cudaFuncAttributeMaxDynamicSharedMemorySize,
                         SMTOT);

    chol_kernel<<<KST, 256>>>(Sigma, b);
    dim3 wgrid(8, KST);
    weff_pack_kernel<<<wgrid, 256>>>(W);
    main_kernel<<<TDIM / TM, 128, SMTOT>>>(x, out);
}

// round 4
// speedup vs baseline: 5.9479x; 1.1879x over previous
#include <cuda_runtime.h>
#include <cuda_fp16.h>
#include <math.h>
#include <stdint.h>

// ---------------- problem constants ----------------
#define KST   16
#define CDIM  64
#define TDIM  65536
#define KTOT  576            // 64*9 contraction length
#define TM    128            // time rows per tile (GEMM M)
#define ASTR  1168           // smem row stride bytes (584 halves)

// ---------------- device scratch ----------------
__device__ float  g_Linv[KST * CDIM * CDIM];
__device__ float  g_logdet[KST];
__device__ float  g_beff[KST * CDIM];
__device__ __half g_WeffH[KST * CDIM * KTOT];   // [k][c][e], e = ci*9+j

// ---------------- helpers ----------------
__device__ __forceinline__ uint32_t s2u(const void* p) {
    uint32_t a;
    asm("{ .reg .u64 t; cvta.to.shared.u64 t, %1; cvt.u32.u64 %0, t; }" : "=r"(a) : "l"(p));
    return a;
}
__device__ __forceinline__ void ldsm4(uint32_t* r, uint32_t addr) {
    asm volatile("ldmatrix.sync.aligned.m8n8.x4.shared.b16 {%0,%1,%2,%3}, [%4];"
                 : "=r"(r[0]), "=r"(r[1]), "=r"(r[2]), "=r"(r[3]) : "r"(addr));
}
__device__ __forceinline__ void mma16816(float* d, const uint32_t* a, const uint32_t* b) {
    asm volatile(
        "mma.sync.aligned.m16n8k16.row.col.f32.f16.f16.f32 "
        "{%0,%1,%2,%3}, {%4,%5,%6,%7}, {%8,%9}, {%0,%1,%2,%3};"
        : "+f"(d[0]), "+f"(d[1]), "+f"(d[2]), "+f"(d[3])
        : "r"(a[0]), "r"(a[1]), "r"(a[2]), "r"(a[3]), "r"(b[0]), "r"(b[1]));
}
__device__ __forceinline__ void cpasync16(uint32_t dst, const void* src) {
    asm volatile("cp.async.cg.shared.global [%0], [%1], 16;" :: "r"(dst), "l"(src));
}
#define CP_COMMIT() asm volatile("cp.async.commit_group;" ::: "memory")
#define CP_WAIT1()  asm volatile("cp.async.wait_group 1;" ::: "memory")

// ================= 1) fast Cholesky + L^{-1} + logdet + beff =================
// Deferred-normalization Cholesky: 1 sync/step. Then rank-1-sweep forward
// substitution for X = L^{-1}: 1 sync/step. All parallel over 256 threads.
__global__ void chol_kernel(const float* __restrict__ Sigma, const float* __restrict__ b) {
    const int k = blockIdx.x;
    const int tid = threadIdx.x;   // 256
    __shared__ float S[CDIM * 65];
    __shared__ float X[CDIM * 65];
    __shared__ float drs[CDIM];
    __shared__ float lgs[CDIM];

    for (int idx = tid; idx < CDIM * CDIM; idx += 256)
        S[(idx >> 6) * 65 + (idx & 63)] = Sigma[k * CDIM * CDIM + idx];
    // init X = I
    for (int idx = tid; idx < CDIM * CDIM; idx += 256)
        X[(idx >> 6) * 65 + (idx & 63)] = ((idx >> 6) == (idx & 63)) ? 1.f : 0.f;
    __syncthreads();

    const int r = tid & 63;
    const int q = tid >> 6;

    // Cholesky with deferred diagonal normalization:
    // after the loop, L[r][c] = S[r][c] / sqrt(S[c][c]).
    for (int kk = 0; kk < CDIM - 1; kk++) {
        const float dinv = 1.f / S[kk * 65 + kk];
        if (r > kk) {
            const float srk = S[r * 65 + kk] * dinv;
            for (int j = kk + 1 + q; j <= r; j += 4)
                S[r * 65 + j] -= srk * S[j * 65 + kk];
        }
        __syncthreads();
    }

    // diag recip-sqrt + log (parallel)
    if (tid < CDIM) {
        const float d = S[tid * 65 + tid];
        drs[tid] = rsqrtf(d);
        lgs[tid] = logf(d);
    }
    __syncthreads();
    if (tid == 0) {
        float ld = 0.f;
        for (int i = 0; i < CDIM; i++) ld += lgs[i];
        g_logdet[k] = ld;     // = 2*sum(log L_ii)
    }

    // forward substitution by rank-1 sweeps: L X = I
    // multiplier L[r][i]/L[i][i] = S[r][i]/S[i][i]
    for (int i = 0; i < CDIM - 1; i++) {
        const float siinv = 1.f / S[i * 65 + i];
        if (r > i) {
            const float mri = S[r * 65 + i] * siinv;
            for (int c = q; c <= i; c += 4)
                X[r * 65 + c] -= mri * X[i * 65 + c];
        }
        __syncthreads();
    }
    // final scaling: X[i][c] /= L[i][i]  (= * drs[i])
    for (int idx = tid; idx < CDIM * CDIM; idx += 256) {
        const int row = idx >> 6, col = idx & 63;
        if (col <= row) X[row * 65 + col] *= drs[row];
        else            X[row * 65 + col] = 0.f;
    }
    __syncthreads();

    if (tid < CDIM) {
        float a = 0.f;
        for (int m = 0; m < CDIM; m++) a += X[tid * 65 + m] * b[k * CDIM + m];
        g_beff[k * CDIM + tid] = a;
    }
    for (int idx = tid; idx < CDIM * CDIM; idx += 256)
        g_Linv[k * CDIM * CDIM + idx] = X[(idx >> 6) * 65 + (idx & 63)];
}

// ========== 2) Weff = Linv @ W -> fp16 packed [k][c][576] ==========
// grid (8 splits, 16 k), 256 threads. Split s covers e in [72s, 72s+72).
__global__ void weff_pack_kernel(const float* __restrict__ W) {
    const int s = blockIdx.x;
    const int k = blockIdx.y;
    const int tid = threadIdx.x;
    __shared__ float Xs[CDIM * 65];
    __shared__ float Ws[CDIM * 73];

    for (int idx = tid; idx < CDIM * CDIM; idx += 256)
        Xs[(idx >> 6) * 65 + (idx & 63)] = g_Linv[k * CDIM * CDIM + idx];
    for (int idx = tid; idx < CDIM * 72; idx += 256) {
        const int m = idx / 72, e = idx - m * 72;
        Ws[m * 73 + e] = W[k * CDIM * KTOT + m * KTOT + s * 72 + e];
    }
    __syncthreads();

    const int c = tid & 63;
    const int grp = tid >> 6;
    float Lr[CDIM];
    #pragma unroll
    for (int m = 0; m < CDIM; m++) Lr[m] = Xs[c * 65 + m];

    for (int eo = grp; eo < 72; eo += 4) {
        float acc = 0.f;
        #pragma unroll
        for (int m = 0; m < CDIM; m++) acc += Lr[m] * Ws[m * 73 + eo];
        g_WeffH[((size_t)k * CDIM + c) * KTOT + s * 72 + eo] = __float2half(acc);
    }
}

// ================= 3) main: smem im2col A + mma.sync fp16, 8 warps =================
// smem bytes: A [0,149504), B [149504,224256), beff, logd, red
#define SMA   0
#define SMB   149504
#define SMBE  224256
#define SMLD  228352
#define SMRED 228416
#define SMTOT 228928

__device__ __forceinline__ void loadB(uint32_t sbB, int k, int h, int tid) {
    // half h: 288 halves per row starting at byte col h*576; 64 rows x 36 chunks
    #pragma unroll
    for (int i = 0; i < 9; i++) {
        const int lin = i * 256 + tid;          // 0..2303
        const int row = lin / 36, ch = lin - row * 36;
        const uint32_t dst = sbB + row * ASTR + h * 576 + ch * 16;
        const char* src = (const char*)g_WeffH +
                          ((size_t)k * CDIM + row) * (KTOT * 2) + h * 576 + ch * 16;
        cpasync16(dst, src);
    }
}

__global__ void __launch_bounds__(256, 1)
main_kernel(const float* __restrict__ x, float* __restrict__ out) {
    extern __shared__ __align__(1024) char smem[];
    const uint32_t sb = s2u(smem);
    const int tid = threadIdx.x;
    const int lane = tid & 31;
    const int w = tid >> 5;           // 8 warps
    const int wm = w & 3;             // M: rows [wm*32, +32)
    const int wn = w >> 2;            // N: cols [wn*32, +32)
    const int t0 = blockIdx.x * TM;

    float* beff_s = (float*)(smem + SMBE);
    float* logd_s = (float*)(smem + SMLD);
    float* red    = (float*)(smem + SMRED);

    // prefetch B for half-steps 0 and 1 (state 0)
    loadB(sb + SMB, 0, 0, tid); CP_COMMIT();
    loadB(sb + SMB, 0, 1, tid); CP_COMMIT();

    // ---- build A (im2col fp16): 2 threads per row, 16 channel-pairs each ----
    {
        const int row = tid >> 1, half = tid & 1;
        __half* Arow = (__half*)(smem + SMA + row * ASTR);
        const int tb = t0 + row - 8;
        #pragma unroll 4
        for (int pp = 0; pp < 16; pp++) {
            const int p = half * 16 + pp;        // channel pair (2p, 2p+1)
            float v[18];
            const float* x0 = x + (size_t)(2 * p) * TDIM;
            const float* x1 = x0 + TDIM;
            #pragma unroll
            for (int j = 0; j < 9; j++) {
                const int gt = tb + j;
                v[j]     = (gt >= 0) ? __ldg(x0 + gt) : 0.f;
                v[9 + j] = (gt >= 0) ? __ldg(x1 + gt) : 0.f;
            }
            uint32_t* dst = (uint32_t*)(Arow + p * 18);   // 36B-aligned
            #pragma unroll
            for (int qq = 0; qq < 9; qq++) {
                __half2 hh = __floats2half2_rn(v[2 * qq], v[2 * qq + 1]);
                dst[qq] = *(uint32_t*)&hh;
            }
        }
    }
    for (int idx = tid; idx < KST * CDIM; idx += 256) beff_s[idx] = g_beff[idx];
    if (tid < KST) logd_s[tid] = g_logdet[tid];

    // ldmatrix per-thread base addresses
    const int mat = lane >> 3, lr = lane & 7;
    const uint32_t aBase = sb + SMA + (wm * 32 + (mat & 1) * 8 + lr) * ASTR + (mat >> 1) * 16;
    const uint32_t bBase = sb + SMB + (wn * 32 + (mat >> 1) * 8 + lr) * ASTR + (mat & 1) * 16;
    const int g = lane >> 2, tig = lane & 3;

    float acc[2][4][4];
    #pragma unroll
    for (int mt = 0; mt < 2; mt++)
        #pragma unroll
        for (int nt = 0; nt < 4; nt++)
            #pragma unroll
            for (int i = 0; i < 4; i++) acc[mt][nt][i] = 0.f;

    CP_WAIT1();              // half-step 0 resident
    __syncthreads();         // A + B(0,0) visible everywhere

    for (int s = 0; s < 2 * KST; s++) {
        const int k = s >> 1, h = s & 1;

        // ---- compute half-step s : k-steps [h*18, h*18+18) ----
        #pragma unroll 3
        for (int kk = h * 18; kk < h * 18 + 18; kk++) {
            uint32_t a[2][4], b[2][4];
            ldsm4(a[0], aBase + kk * 32);
            ldsm4(a[1], aBase + 16 * ASTR + kk * 32);
            ldsm4(b[0], bBase + kk * 32);
            ldsm4(b[1], bBase + 16 * ASTR + kk * 32);
            #pragma unroll
            for (int mt = 0; mt < 2; mt++)
                #pragma unroll
                for (int nt = 0; nt < 4; nt++)
                    mma16816(acc[mt][nt], a[mt], &b[nt >> 1][(nt & 1) * 2]);
        }

        // ---- epilogue at end of each state ----
        if (h == 1) {
            const float ld = logd_s[k];
            float be[4][2];
            #pragma unroll
            for (int nt = 0; nt < 4; nt++) {
                float2 v = *(const float2*)&beff_s[k * CDIM + wn * 32 + nt * 8 + tig * 2];
                be[nt][0] = v.x; be[nt][1] = v.y;
            }
            float ps[2][2];
            #pragma unroll
            for (int mt = 0; mt < 2; mt++)
                #pragma unroll
                for (int rh = 0; rh < 2; rh++) {
                    float sum = 0.f;
                    #pragma unroll
                    for (int nt = 0; nt < 4; nt++) {
                        const float z0 = acc[mt][nt][rh * 2 + 0] + be[nt][0];
                        const float z1 = acc[mt][nt][rh * 2 + 1] + be[nt][1];
                        sum = fmaf(z0, z0, sum);
                        sum = fmaf(z1, z1, sum);
                        acc[mt][nt][rh * 2 + 0] = 0.f;
                        acc[mt][nt][rh * 2 + 1] = 0.f;
                    }
                    sum += __shfl_xor_sync(0xffffffffu, sum, 1);
                    sum += __shfl_xor_sync(0xffffffffu, sum, 2);
                    ps[mt][rh] = sum;     // valid in all 4 tig lanes
                }
            // combine the two N-half warps via smem
            if (wn == 0 && tig == 0) {
                #pragma unroll
                for (int mt = 0; mt < 2; mt++)
                    #pragma unroll
                    for (int rh = 0; rh < 2; rh++)
                        red[wm * 32 + mt * 16 + rh * 8 + g] = ps[mt][rh];
            }
            __syncthreads();
            if (wn == 1 && tig == 0) {
                #pragma unroll
                for (int mt = 0; mt < 2; mt++)
                    #pragma unroll
                    for (int rh = 0; rh < 2; rh++) {
                        const int row = wm * 32 + mt * 16 + rh * 8 + g;
                        out[(size_t)k * TDIM + t0 + row] =
                            -0.5f * (117.62413225f + ld + red[row] + ps[mt][rh]);
                    }
            }
        }

        __syncthreads();                         // everyone done with buffer of s
        if (s + 2 < 2 * KST) {
            const int s2 = s + 2;
            loadB(sb + SMB, s2 >> 1, s2 & 1, tid);   // reuses buffer of s
        }
        CP_COMMIT();
        if (s + 1 < 2 * KST) {
            CP_WAIT1();                          // half-step s+1 resident
            __syncthreads();
        }
    }
}

// ---------------- launch ----------------
extern "C" void kernel_launch(void* const* d_in, const int* in_sizes, int n_in,
                              void* d_out, int out_size) {
    const float* x     = (const float*)d_in[0];  // [1,64,65536]
    const float* W     = (const float*)d_in[1];  // [16,64,64,9]
    const float* b     = (const float*)d_in[2];  // [16,64]
    const float* Sigma = (const float*)d_in[3];  // [16,64,64]
    float* out = (float*)d_out;                  // [1,16,65536]
    (void)in_sizes; (void)n_in; (void)out_size;

    cudaFuncSetAttribute(main_kernel, cudaFuncAttributeMaxDynamicSharedMemorySize,
                         SMTOT);

    chol_kernel<<<KST, 256>>>(Sigma, b);
    dim3 wgrid(8, KST);
    weff_pack_kernel<<<wgrid, 256>>>(W);
    main_kernel<<<TDIM / TM, 256, SMTOT>>>(x, out);
}